// round 11
// baseline (speedup 1.0000x reference)
#include <cuda_runtime.h>
#include <cuda_bf16.h>
#include <math.h>
#include <stdint.h>

#define TL 50
#define TD 200
#define KSPAD 216         // A row stride in SMEM (bf16) -> 432B, ldsm conflict-free
#define NBLK 3
#define NTHREADS 512
#define WS 204
#define SSTRIDE 52
#define NEGV (-4294967296.0f)
#define LNEPS 1e-8f
#define KSTEPS 13         // 13 x k16 = 208
#define NTILES 25         // 25 x n8 = 200
#define MATSTRIDE (NTILES * KSTEPS * 32)   // uint4 per weight matrix

// SMEM byte offsets
#define SM_AHI 0
#define SM_ALO 27648                    // 64*216*2
#define SM_SX  55296
#define SM_A   (SM_SX + 40800)          // 96096
#define SM_B   (SM_A + 40800)           // 136896
#define SM_V   (SM_B + 40800)           // 177696
#define SM_SS  (SM_V + 40800)           // 218496
#define SM_KM  (SM_SS + 10400)          // 228896
#define SM_TOTAL (SM_KM + 256)          // 229152

// Fragment-packed weights: [mat(15)][nt(25)][ks(13)][lane(32)] = {bh0,bh1,bl0,bl1}
__device__ uint4 g_wfrag[15 * MATSTRIDE];

// ---------------- SIMT helpers ----------------
__device__ __forceinline__ float wsum(float v) {
#pragma unroll
    for (int o = 16; o > 0; o >>= 1) v += __shfl_xor_sync(0xffffffffu, v, o);
    return v;
}
__device__ __forceinline__ float wmax(float v) {
#pragma unroll
    for (int o = 16; o > 0; o >>= 1) v = fmaxf(v, __shfl_xor_sync(0xffffffffu, v, o));
    return v;
}
__device__ __forceinline__ void ffma2(uint64_t& acc, uint64_t a, uint64_t b) {
    asm("fma.rn.f32x2 %0, %1, %2, %0;" : "+l"(acc) : "l"(a), "l"(b));
}
__device__ __forceinline__ uint64_t rep2(float x) {
    uint64_t r; asm("mov.b64 %0, {%1, %1};" : "=l"(r) : "f"(x)); return r;
}
__device__ __forceinline__ uint64_t pack2(float lo, float hi) {
    uint64_t r; asm("mov.b64 %0, {%1, %2};" : "=l"(r) : "f"(lo), "f"(hi)); return r;
}
__device__ __forceinline__ void unpack2(uint64_t v, float& lo, float& hi) {
    asm("mov.b64 {%0, %1}, %2;" : "=f"(lo), "=f"(hi) : "l"(v));
}

// ---------------- MMA helpers ----------------
__device__ __forceinline__ void ldsm_x4(uint32_t r[4], uint32_t addr) {
    asm volatile("ldmatrix.sync.aligned.m8n8.x4.shared.b16 {%0,%1,%2,%3}, [%4];"
                 : "=r"(r[0]), "=r"(r[1]), "=r"(r[2]), "=r"(r[3]) : "r"(addr));
}
__device__ __forceinline__ void mma16816(float c[4], const uint32_t a[4],
                                         uint32_t b0, uint32_t b1) {
    asm volatile(
        "mma.sync.aligned.m16n8k16.row.col.f32.bf16.bf16.f32 "
        "{%0,%1,%2,%3}, {%4,%5,%6,%7}, {%8,%9}, {%0,%1,%2,%3};"
        : "+f"(c[0]), "+f"(c[1]), "+f"(c[2]), "+f"(c[3])
        : "r"(a[0]), "r"(a[1]), "r"(a[2]), "r"(a[3]), "r"(b0), "r"(b1));
}
__device__ __forceinline__ uint32_t cvt_bf16x2(float hi, float lo) {
    uint32_t h;
    asm("cvt.rn.satfinite.bf16x2.f32 %0, %1, %2;" : "=r"(h) : "f"(hi), "f"(lo));
    return h;
}

// ---------------- prep kernel: W[k][n] f32 -> fragment-packed bf16 hi/lo ----------------
// grid (15, 25), 416 threads (13 warps: warp = ks)
__global__ void prep_kernel(const float* __restrict__ Wq, const float* __restrict__ Wk,
                            const float* __restrict__ Wv, const float* __restrict__ W1,
                            const float* __restrict__ W2) {
    const int mat = blockIdx.x;       // 0..14
    const int nt = blockIdx.y;        // 0..24
    const int blk = mat / 5, wh = mat % 5;
    const float* W = (wh == 0 ? Wq : wh == 1 ? Wk : wh == 2 ? Wv : wh == 3 ? W1 : W2)
                     + blk * TD * TD;
    const int ks = threadIdx.x >> 5;  // 0..12
    const int lane = threadIdx.x & 31;
    const int gid = lane >> 2, tig = lane & 3;
    const int n = nt * 8 + gid;
    const int k0 = ks * 16 + 2 * tig;

    auto rd = [&](int k) -> float { return (k < TD) ? __ldg(W + k * TD + n) : 0.0f; };
    const float v0 = rd(k0),     v1 = rd(k0 + 1);
    const float v2 = rd(k0 + 8), v3 = rd(k0 + 9);

    const uint32_t bh0 = cvt_bf16x2(v1, v0);
    const uint32_t bh1 = cvt_bf16x2(v3, v2);
    const float h0 = __uint_as_float(bh0 << 16), h1 = __uint_as_float(bh0 & 0xffff0000u);
    const float h2 = __uint_as_float(bh1 << 16), h3 = __uint_as_float(bh1 & 0xffff0000u);
    const uint32_t bl0 = cvt_bf16x2(v1 - h1, v0 - h0);
    const uint32_t bl1 = cvt_bf16x2(v3 - h3, v2 - h2);

    g_wfrag[(size_t)mat * MATSTRIDE + (nt * KSTEPS + ks) * 32 + lane] =
        make_uint4(bh0, bh1, bl0, bl1);
}

// ---------------- convert A: f32 (stride WS) -> bf16 hi/lo SMEM [64][KSPAD] ----------------
__device__ __forceinline__ void convert_A(const float* __restrict__ src,
                                          char* smem, int tid) {
    __nv_bfloat16* hi = (__nv_bfloat16*)(smem + SM_AHI);
    __nv_bfloat16* lo = (__nv_bfloat16*)(smem + SM_ALO);
    for (int idx = tid; idx < TL * (TD / 2); idx += NTHREADS) {
        const int row = idx / (TD / 2);
        const int c2 = (idx - row * (TD / 2)) * 2;
        const float x0 = src[row * WS + c2];
        const float x1 = src[row * WS + c2 + 1];
        const uint32_t h = cvt_bf16x2(x1, x0);
        const float h0 = __uint_as_float(h << 16);
        const float h1 = __uint_as_float(h & 0xffff0000u);
        const uint32_t l = cvt_bf16x2(x1 - h1, x0 - h0);
        *(uint32_t*)(hi + row * KSPAD + c2) = h;
        *(uint32_t*)(lo + row * KSPAD + c2) = l;
    }
}

// ---------------- fused tensor-core GEMM over NM weight matrices ----------------
// A: SMEM bf16 hi/lo [64][KSPAD]; B: g_wfrag fragments (consecutive mats from fb).
// Work units: 48 = (nt 0..23) x (m-half 0/2), 3 per warp exactly; tail nt=24
// split into 4 single-mt units for warps 0..3 (one per SMSP -> SMSP-balanced).
// B fragments register-prefetched one ks ahead.
template<int NM, bool RELU>
__device__ __forceinline__ void gemm_mma_f(
    const uint4* __restrict__ fb,
    float* const* dsts, const float* const* biases,
    uint32_t smem_u32, int tid)
{
    const int w = tid >> 5, lane = tid & 31;
    const int gid = lane >> 2, tig = lane & 3;
    const uint32_t abase = smem_u32 + ((uint32_t)((lane & 15) * KSPAD + (lane >> 4) * 8)) * 2u;

#pragma unroll 1
    for (int u = w; u < 48; u += 16) {
        const int nt = u >> 1;
        const int mh = (u & 1) * 2;
        float c[NM][2][4];
#pragma unroll
        for (int m = 0; m < NM; m++)
#pragma unroll
            for (int t2 = 0; t2 < 2; t2++)
#pragma unroll
                for (int j = 0; j < 4; j++) c[m][t2][j] = 0.0f;

        const uint4* fr = fb + nt * (KSTEPS * 32) + lane;
        uint4 pb[NM];
#pragma unroll
        for (int m = 0; m < NM; m++) pb[m] = __ldg(fr + (size_t)m * MATSTRIDE);

#pragma unroll 1
        for (int ks = 0; ks < KSTEPS; ks++) {
            uint4 bf[NM];
#pragma unroll
            for (int m = 0; m < NM; m++) bf[m] = pb[m];
            if (ks + 1 < KSTEPS) {
#pragma unroll
                for (int m = 0; m < NM; m++)
                    pb[m] = __ldg(fr + (size_t)m * MATSTRIDE + (ks + 1) * 32);
            }
            const uint32_t koff = (uint32_t)(ks * 32);
#pragma unroll
            for (int t2 = 0; t2 < 2; t2++) {
                const int mt = mh + t2;
                uint32_t ah[4], al[4];
                const uint32_t aoff = (uint32_t)(mt * 16 * KSPAD * 2) + koff;
                ldsm_x4(ah, abase + SM_AHI + aoff);
                ldsm_x4(al, abase + SM_ALO + aoff);
#pragma unroll
                for (int m = 0; m < NM; m++) {
                    mma16816(c[m][t2], ah, bf[m].x, bf[m].y);
                    mma16816(c[m][t2], al, bf[m].x, bf[m].y);
                    mma16816(c[m][t2], ah, bf[m].z, bf[m].w);
                }
            }
        }

        const int col0 = nt * 8 + 2 * tig;
#pragma unroll
        for (int m = 0; m < NM; m++) {
            const float bx = __ldg(biases[m] + col0);
            const float by = __ldg(biases[m] + col0 + 1);
            float* dst = dsts[m];
#pragma unroll
            for (int t2 = 0; t2 < 2; t2++) {
                const int mt = mh + t2;
                const int r0 = mt * 16 + gid;
                if (r0 < TL) {
                    float v0 = c[m][t2][0] + bx, v1 = c[m][t2][1] + by;
                    if (RELU) { v0 = fmaxf(v0, 0.0f); v1 = fmaxf(v1, 0.0f); }
                    dst[r0 * WS + col0] = v0;
                    dst[r0 * WS + col0 + 1] = v1;
                }
                const int r1 = mt * 16 + gid + 8;
                if (r1 < TL) {
                    float v2 = c[m][t2][2] + bx, v3 = c[m][t2][3] + by;
                    if (RELU) { v2 = fmaxf(v2, 0.0f); v3 = fmaxf(v3, 0.0f); }
                    dst[r1 * WS + col0] = v2;
                    dst[r1 * WS + col0 + 1] = v3;
                }
            }
        }
    }

    // tail: nt = 24, one mt per warp for warps 0..3 (one per SMSP)
    if (w < 4) {
        const int nt = 24, mt = w;
        float c[NM][4];
#pragma unroll
        for (int m = 0; m < NM; m++)
#pragma unroll
            for (int j = 0; j < 4; j++) c[m][j] = 0.0f;

        const uint4* fr = fb + nt * (KSTEPS * 32) + lane;
        uint4 pb[NM];
#pragma unroll
        for (int m = 0; m < NM; m++) pb[m] = __ldg(fr + (size_t)m * MATSTRIDE);

#pragma unroll 1
        for (int ks = 0; ks < KSTEPS; ks++) {
            uint4 bf[NM];
#pragma unroll
            for (int m = 0; m < NM; m++) bf[m] = pb[m];
            if (ks + 1 < KSTEPS) {
#pragma unroll
                for (int m = 0; m < NM; m++)
                    pb[m] = __ldg(fr + (size_t)m * MATSTRIDE + (ks + 1) * 32);
            }
            uint32_t ah[4], al[4];
            const uint32_t aoff = (uint32_t)(mt * 16 * KSPAD * 2) + (uint32_t)(ks * 32);
            ldsm_x4(ah, abase + SM_AHI + aoff);
            ldsm_x4(al, abase + SM_ALO + aoff);
#pragma unroll
            for (int m = 0; m < NM; m++) {
                mma16816(c[m], ah, bf[m].x, bf[m].y);
                mma16816(c[m], al, bf[m].x, bf[m].y);
                mma16816(c[m], ah, bf[m].z, bf[m].w);
            }
        }

        const int col0 = nt * 8 + 2 * tig;
#pragma unroll
        for (int m = 0; m < NM; m++) {
            const float bx = __ldg(biases[m] + col0);
            const float by = __ldg(biases[m] + col0 + 1);
            float* dst = dsts[m];
            const int r0 = mt * 16 + gid;
            if (r0 < TL) {
                float v0 = c[m][0] + bx, v1 = c[m][1] + by;
                if (RELU) { v0 = fmaxf(v0, 0.0f); v1 = fmaxf(v1, 0.0f); }
                dst[r0 * WS + col0] = v0;
                dst[r0 * WS + col0 + 1] = v1;
            }
            const int r1 = mt * 16 + gid + 8;
            if (r1 < TL) {
                float v2 = c[m][2] + bx, v3 = c[m][3] + by;
                if (RELU) { v2 = fmaxf(v2, 0.0f); v3 = fmaxf(v3, 0.0f); }
                dst[r1 * WS + col0] = v2;
                dst[r1 * WS + col0 + 1] = v3;
            }
        }
    }
}

// ---------------- main kernel ----------------
__global__ void __launch_bounds__(NTHREADS, 1) encoder_kernel(
    const int* __restrict__ tokens, const float* __restrict__ emb,
    const float* __restrict__ bq, const float* __restrict__ bk,
    const float* __restrict__ bv, const float* __restrict__ b1,
    const float* __restrict__ b2,
    const float* __restrict__ lng, const float* __restrict__ lnb,
    float* __restrict__ out)
{
    extern __shared__ char smem[];
    const uint32_t smem_u32 = (uint32_t)__cvta_generic_to_shared(smem);
    float* sx   = (float*)(smem + SM_SX);
    float* bufA = (float*)(smem + SM_A);
    float* bufB = (float*)(smem + SM_B);
    float* bufV = (float*)(smem + SM_V);
    float* sS   = (float*)(smem + SM_SS);
    float* km   = (float*)(smem + SM_KM);

    const int tid = threadIdx.x;
    const int b = blockIdx.x;
    const int warp = tid >> 5, lane = tid & 31;

    // zero A bf16 buffers (padding rows/cols stay zero forever)
    {
        uint32_t* az = (uint32_t*)(smem + SM_AHI);
        for (int i = tid; i < (2 * 64 * KSPAD) / 2; i += NTHREADS) az[i] = 0u;
    }
    // Embedding gather: sx = emb[tokens[b]]  (stride WS)
    {
        const int* tok = tokens + b * TL;
        for (int idx = tid; idx < TL * (TD / 4); idx += NTHREADS) {
            const int m = idx / (TD / 4);
            const int c = idx - m * (TD / 4);
            const int t = __ldg(tok + m);
            *(float4*)(sx + m * WS + c * 4) =
                __ldg((const float4*)emb + (size_t)t * (TD / 4) + c);
        }
    }
    __syncthreads();

    for (int blk = 0; blk < NBLK; blk++) {
        const int m0 = blk * 5;
        const float* bq_ = bq + blk * TD;
        const float* bk_ = bk + blk * TD;
        const float* bv_ = bv + blk * TD;
        const float* b1_ = b1 + blk * TD;
        const float* b2_ = b2 + blk * TD;
        const float* g_  = lng + blk * TD;
        const float* be_ = lnb + blk * TD;

        // Row masks: km[r] = 1 if sum(x[r,:]) == 0
        for (int r = warp; r < TL; r += NTHREADS / 32) {
            float s = 0.0f;
            for (int c = lane; c < TD; c += 32) s += sx[r * WS + c];
            s = wsum(s);
            if (lane == 0) km[r] = (s == 0.0f) ? 1.0f : 0.0f;
        }
        convert_A(sx, smem, tid);
        __syncthreads();

        // Fused Q|K|V on tensor cores
        {
            float* dsts[3] = {bufA, bufB, bufV};
            const float* biases[3] = {bq_, bk_, bv_};
            gemm_mma_f<3, true>(g_wfrag + (size_t)m0 * MATSTRIDE, dsts, biases,
                                smem_u32, tid);
        }
        __syncthreads();

        // scores = (Q @ K^T)*scale with key mask  (SIMT FFMA2)
        if (tid < 500) {
            const int q = tid / 10;
            const int kk0 = (tid % 10) * 5;
            uint64_t acc[5] = {0ull, 0ull, 0ull, 0ull, 0ull};
#pragma unroll 2
            for (int d = 0; d < TD; d += 4) {
                const float4 qa = *(const float4*)(bufA + q * WS + d);
                const uint64_t q01 = pack2(qa.x, qa.y);
                const uint64_t q23 = pack2(qa.z, qa.w);
#pragma unroll
                for (int j = 0; j < 5; j++) {
                    const float4 kv = *(const float4*)(bufB + (kk0 + j) * WS + d);
                    ffma2(acc[j], q01, pack2(kv.x, kv.y));
                    ffma2(acc[j], q23, pack2(kv.z, kv.w));
                }
            }
            const float scale = 0.07071067811865475f;  // 1/sqrt(200)
#pragma unroll
            for (int j = 0; j < 5; j++) {
                float l, h;
                unpack2(acc[j], l, h);
                sS[q * SSTRIDE + kk0 + j] =
                    (km[kk0 + j] != 0.0f) ? NEGV : (l + h) * scale;
            }
        }
        __syncthreads();

        // Softmax rows + query mask
        for (int q = warp; q < TL; q += NTHREADS / 32) {
            const float a  = sS[q * SSTRIDE + lane];
            const float bb = (lane < TL - 32) ? sS[q * SSTRIDE + 32 + lane] : -3.4e38f;
            const float mx = wmax(fmaxf(a, bb));
            const float ea = expf(a - mx);
            const float eb = (lane < TL - 32) ? expf(bb - mx) : 0.0f;
            const float ssum = wsum(ea + eb);
            const float fac = (1.0f - km[q]) / ssum;
            sS[q * SSTRIDE + lane] = ea * fac;
            if (lane < TL - 32) sS[q * SSTRIDE + 32 + lane] = eb * fac;
        }
        __syncthreads();

        // x += attn @ V  (SIMT FFMA2)
        if (tid < 500) {
            const int cg = tid % 50, rg = tid / 50;
            const int n0 = cg * 4, mr = rg * 5;
            uint64_t acc[5][2];
#pragma unroll
            for (int i = 0; i < 5; i++) { acc[i][0] = 0ull; acc[i][1] = 0ull; }
#pragma unroll 2
            for (int kk = 0; kk < TL; kk++) {
                const float4 v = *(const float4*)(bufV + kk * WS + n0);
                const uint64_t v01 = pack2(v.x, v.y);
                const uint64_t v23 = pack2(v.z, v.w);
#pragma unroll
                for (int i = 0; i < 5; i++) {
                    const uint64_t a = rep2(sS[(mr + i) * SSTRIDE + kk]);
                    ffma2(acc[i][0], a, v01);
                    ffma2(acc[i][1], a, v23);
                }
            }
#pragma unroll
            for (int i = 0; i < 5; i++) {
                float a0, a1, a2, a3;
                unpack2(acc[i][0], a0, a1);
                unpack2(acc[i][1], a2, a3);
                float* o = sx + (mr + i) * WS + n0;
                o[0] += a0; o[1] += a1; o[2] += a2; o[3] += a3;
            }
        }
        __syncthreads();

        // FFN1: h1 = relu(x @ W1 + b1) -> bufA
        convert_A(sx, smem, tid);
        __syncthreads();
        {
            float* dsts[1] = {bufA};
            const float* biases[1] = {b1_};
            gemm_mma_f<1, true>(g_wfrag + (size_t)(m0 + 3) * MATSTRIDE, dsts, biases,
                                smem_u32, tid);
        }
        __syncthreads();

        // FFN2: h2 = h1 @ W2 + b2 -> bufB
        convert_A(bufA, smem, tid);
        __syncthreads();
        {
            float* dsts[1] = {bufB};
            const float* biases[1] = {b2_};
            gemm_mma_f<1, false>(g_wfrag + (size_t)(m0 + 4) * MATSTRIDE, dsts, biases,
                                 smem_u32, tid);
        }
        __syncthreads();

        // LayerNorm(h2)*g + be, residual into sx
        for (int r = warp; r < TL; r += NTHREADS / 32) {
            float hbuf[7];
            int nc = 0;
            float s = 0.0f;
            for (int c = lane; c < TD; c += 32) {
                const float h = bufB[r * WS + c];
                hbuf[nc++] = h;
                s += h;
            }
            s = wsum(s);
            const float mu = s * (1.0f / TD);
            float v = 0.0f;
            for (int i = 0; i < nc; i++) {
                const float dd = hbuf[i] - mu;
                v = fmaf(dd, dd, v);
            }
            v = wsum(v);
            const float inv = rsqrtf(v * (1.0f / TD) + LNEPS);
            nc = 0;
            for (int c = lane; c < TD; c += 32) {
                const float y = (hbuf[nc++] - mu) * inv * __ldg(g_ + c) + __ldg(be_ + c);
                sx[r * WS + c] += y;
            }
        }
        __syncthreads();
    }

    // Write out (dense 200 stride)
    {
        float4* o = (float4*)(out + (size_t)b * TL * TD);
        for (int idx = tid; idx < TL * (TD / 4); idx += NTHREADS) {
            const int m = idx / (TD / 4);
            const int c = idx - m * (TD / 4);
            o[idx] = *(const float4*)(sx + m * WS + c * 4);
        }
    }
}

extern "C" void kernel_launch(void* const* d_in, const int* in_sizes, int n_in,
                              void* d_out, int out_size) {
    const int*   tokens = (const int*)d_in[0];
    const float* emb = (const float*)d_in[1];
    const float* Wq  = (const float*)d_in[2];
    const float* bq  = (const float*)d_in[3];
    const float* Wk  = (const float*)d_in[4];
    const float* bk  = (const float*)d_in[5];
    const float* Wv  = (const float*)d_in[6];
    const float* bv  = (const float*)d_in[7];
    const float* W1  = (const float*)d_in[8];
    const float* b1  = (const float*)d_in[9];
    const float* W2  = (const float*)d_in[10];
    const float* b2  = (const float*)d_in[11];
    const float* lng = (const float*)d_in[12];
    const float* lnb = (const float*)d_in[13];
    float* out = (float*)d_out;

    const int B = in_sizes[0] / TL;

    dim3 pgrid(15, NTILES, 1);
    prep_kernel<<<pgrid, 13 * 32>>>(Wq, Wk, Wv, W1, W2);

    cudaFuncSetAttribute(encoder_kernel,
                         cudaFuncAttributeMaxDynamicSharedMemorySize, SM_TOTAL);
    encoder_kernel<<<B, NTHREADS, SM_TOTAL>>>(tokens, emb, bq, bk, bv, b1, b2,
                                              lng, lnb, out);
}

// round 12
// speedup vs baseline: 1.2408x; 1.2408x over previous
#include <cuda_runtime.h>
#include <cuda_bf16.h>
#include <math.h>
#include <stdint.h>

#define TL 50
#define TD 200
#define KSPAD 216         // A row stride in SMEM (bf16) -> 432B, ldsm conflict-free
#define NBLK 3
#define NTHREADS 512
#define WS 204
#define SSTRIDE 52
#define NEGV (-4294967296.0f)
#define LNEPS 1e-8f
#define KSTEPS 13         // 13 x k16 = 208
#define NTILES 25         // 25 x n8 = 200
#define MATSTRIDE (NTILES * KSTEPS * 32)   // uint4 per weight matrix

// SMEM byte offsets
#define SM_AHI 0
#define SM_ALO 27648                    // 64*216*2
#define SM_SX  55296
#define SM_A   (SM_SX + 40800)          // 96096
#define SM_B   (SM_A + 40800)           // 136896
#define SM_V   (SM_B + 40800)           // 177696
#define SM_SS  (SM_V + 40800)           // 218496
#define SM_KM  (SM_SS + 10400)          // 228896
#define SM_TOTAL (SM_KM + 256)          // 229152

// Fragment-packed weights: [mat(15)][nt(25)][ks(13)][lane(32)] = {bh0,bh1,bl0,bl1}
__device__ uint4 g_wfrag[15 * MATSTRIDE];

// ---------------- SIMT helpers ----------------
__device__ __forceinline__ float wsum(float v) {
#pragma unroll
    for (int o = 16; o > 0; o >>= 1) v += __shfl_xor_sync(0xffffffffu, v, o);
    return v;
}
__device__ __forceinline__ float wmax(float v) {
#pragma unroll
    for (int o = 16; o > 0; o >>= 1) v = fmaxf(v, __shfl_xor_sync(0xffffffffu, v, o));
    return v;
}
__device__ __forceinline__ void ffma2(uint64_t& acc, uint64_t a, uint64_t b) {
    asm("fma.rn.f32x2 %0, %1, %2, %0;" : "+l"(acc) : "l"(a), "l"(b));
}
__device__ __forceinline__ uint64_t rep2(float x) {
    uint64_t r; asm("mov.b64 %0, {%1, %1};" : "=l"(r) : "f"(x)); return r;
}
__device__ __forceinline__ uint64_t pack2(float lo, float hi) {
    uint64_t r; asm("mov.b64 %0, {%1, %2};" : "=l"(r) : "f"(lo), "f"(hi)); return r;
}
__device__ __forceinline__ void unpack2(uint64_t v, float& lo, float& hi) {
    asm("mov.b64 {%0, %1}, %2;" : "=f"(lo), "=f"(hi) : "l"(v));
}

// ---------------- MMA helpers ----------------
__device__ __forceinline__ void ldsm_x4(uint32_t r[4], uint32_t addr) {
    asm volatile("ldmatrix.sync.aligned.m8n8.x4.shared.b16 {%0,%1,%2,%3}, [%4];"
                 : "=r"(r[0]), "=r"(r[1]), "=r"(r[2]), "=r"(r[3]) : "r"(addr));
}
__device__ __forceinline__ void mma16816(float c[4], const uint32_t a[4],
                                         uint32_t b0, uint32_t b1) {
    asm volatile(
        "mma.sync.aligned.m16n8k16.row.col.f32.bf16.bf16.f32 "
        "{%0,%1,%2,%3}, {%4,%5,%6,%7}, {%8,%9}, {%0,%1,%2,%3};"
        : "+f"(c[0]), "+f"(c[1]), "+f"(c[2]), "+f"(c[3])
        : "r"(a[0]), "r"(a[1]), "r"(a[2]), "r"(a[3]), "r"(b0), "r"(b1));
}
__device__ __forceinline__ uint32_t cvt_bf16x2(float hi, float lo) {
    uint32_t h;
    asm("cvt.rn.satfinite.bf16x2.f32 %0, %1, %2;" : "=r"(h) : "f"(hi), "f"(lo));
    return h;
}

// ---------------- prep kernel: W[k][n] f32 -> fragment-packed bf16 hi/lo ----------------
// grid (15, 25), 416 threads (13 warps: warp = ks)
__global__ void prep_kernel(const float* __restrict__ Wq, const float* __restrict__ Wk,
                            const float* __restrict__ Wv, const float* __restrict__ W1,
                            const float* __restrict__ W2) {
    const int mat = blockIdx.x;       // 0..14
    const int nt = blockIdx.y;        // 0..24
    const int blk = mat / 5, wh = mat % 5;
    const float* W = (wh == 0 ? Wq : wh == 1 ? Wk : wh == 2 ? Wv : wh == 3 ? W1 : W2)
                     + blk * TD * TD;
    const int ks = threadIdx.x >> 5;  // 0..12
    const int lane = threadIdx.x & 31;
    const int gid = lane >> 2, tig = lane & 3;
    const int n = nt * 8 + gid;
    const int k0 = ks * 16 + 2 * tig;

    auto rd = [&](int k) -> float { return (k < TD) ? __ldg(W + k * TD + n) : 0.0f; };
    const float v0 = rd(k0),     v1 = rd(k0 + 1);
    const float v2 = rd(k0 + 8), v3 = rd(k0 + 9);

    const uint32_t bh0 = cvt_bf16x2(v1, v0);
    const uint32_t bh1 = cvt_bf16x2(v3, v2);
    const float h0 = __uint_as_float(bh0 << 16), h1 = __uint_as_float(bh0 & 0xffff0000u);
    const float h2 = __uint_as_float(bh1 << 16), h3 = __uint_as_float(bh1 & 0xffff0000u);
    const uint32_t bl0 = cvt_bf16x2(v1 - h1, v0 - h0);
    const uint32_t bl1 = cvt_bf16x2(v3 - h3, v2 - h2);

    g_wfrag[(size_t)mat * MATSTRIDE + (nt * KSTEPS + ks) * 32 + lane] =
        make_uint4(bh0, bh1, bl0, bl1);
}

// ---------------- convert A: f32 (stride WS) -> bf16 hi/lo SMEM [64][KSPAD] ----------------
__device__ __forceinline__ void convert_A(const float* __restrict__ src,
                                          char* smem, int tid) {
    __nv_bfloat16* hi = (__nv_bfloat16*)(smem + SM_AHI);
    __nv_bfloat16* lo = (__nv_bfloat16*)(smem + SM_ALO);
    for (int idx = tid; idx < TL * (TD / 2); idx += NTHREADS) {
        const int row = idx / (TD / 2);
        const int c2 = (idx - row * (TD / 2)) * 2;
        const float x0 = src[row * WS + c2];
        const float x1 = src[row * WS + c2 + 1];
        const uint32_t h = cvt_bf16x2(x1, x0);
        const float h0 = __uint_as_float(h << 16);
        const float h1 = __uint_as_float(h & 0xffff0000u);
        const uint32_t l = cvt_bf16x2(x1 - h1, x0 - h0);
        *(uint32_t*)(hi + row * KSPAD + c2) = h;
        *(uint32_t*)(lo + row * KSPAD + c2) = l;
    }
}

// ---------------- one ks step over 4 m-tiles for NM matrices ----------------
template<int NM>
__device__ __forceinline__ void mma_ksblock(
    float (&c)[NM][4][4], const uint4 (&bf)[NM], uint32_t abase, int ks)
{
    const uint32_t koff = (uint32_t)(ks * 32);
#pragma unroll
    for (int mt = 0; mt < 4; mt++) {
        uint32_t ah[4], al[4];
        const uint32_t aoff = (uint32_t)(mt * 16 * KSPAD * 2) + koff;
        ldsm_x4(ah, abase + SM_AHI + aoff);
        ldsm_x4(al, abase + SM_ALO + aoff);
#pragma unroll
        for (int m = 0; m < NM; m++) {
            mma16816(c[m][mt], ah, bf[m].x, bf[m].y);
            mma16816(c[m][mt], al, bf[m].x, bf[m].y);
            mma16816(c[m][mt], ah, bf[m].z, bf[m].w);
        }
    }
}

// ---------------- fused tensor-core GEMM over NM weight matrices ----------------
// A: SMEM bf16 hi/lo [64][KSPAD]; B: g_wfrag fragments (consecutive mats from fb).
// 16 warps; warp w owns n8-tiles {w, w+16}. B fragments ping-pong prefetched
// one ks-block ahead (unroll-2, no register copies).
template<int NM, bool RELU>
__device__ __forceinline__ void gemm_mma_f(
    const uint4* __restrict__ fb,
    float* const* dsts, const float* const* biases,
    uint32_t smem_u32, int tid)
{
    const int w = tid >> 5, lane = tid & 31;
    const int gid = lane >> 2, tig = lane & 3;
    const uint32_t abase = smem_u32 + ((uint32_t)((lane & 15) * KSPAD + (lane >> 4) * 8)) * 2u;

#pragma unroll 1
    for (int nt = w; nt < NTILES; nt += 16) {
        float c[NM][4][4];
#pragma unroll
        for (int m = 0; m < NM; m++)
#pragma unroll
            for (int mt = 0; mt < 4; mt++)
#pragma unroll
                for (int j = 0; j < 4; j++) c[m][mt][j] = 0.0f;

        const uint4* fr = fb + nt * (KSTEPS * 32) + lane;
        uint4 b0[NM], b1[NM];
#pragma unroll
        for (int m = 0; m < NM; m++) b0[m] = __ldg(fr + (size_t)m * MATSTRIDE);

#pragma unroll 1
        for (int ks = 0; ks < KSTEPS - 1; ks += 2) {
#pragma unroll
            for (int m = 0; m < NM; m++)
                b1[m] = __ldg(fr + (size_t)m * MATSTRIDE + (ks + 1) * 32);
            mma_ksblock<NM>(c, b0, abase, ks);
#pragma unroll
            for (int m = 0; m < NM; m++)
                b0[m] = __ldg(fr + (size_t)m * MATSTRIDE + (ks + 2) * 32);
            mma_ksblock<NM>(c, b1, abase, ks + 1);
        }
        mma_ksblock<NM>(c, b0, abase, KSTEPS - 1);

        const int col0 = nt * 8 + 2 * tig;
#pragma unroll
        for (int m = 0; m < NM; m++) {
            const float bx = __ldg(biases[m] + col0);
            const float by = __ldg(biases[m] + col0 + 1);
            float* dst = dsts[m];
#pragma unroll
            for (int mt = 0; mt < 4; mt++) {
                const int r0 = mt * 16 + gid;
                if (r0 < TL) {
                    float v0 = c[m][mt][0] + bx, v1 = c[m][mt][1] + by;
                    if (RELU) { v0 = fmaxf(v0, 0.0f); v1 = fmaxf(v1, 0.0f); }
                    dst[r0 * WS + col0] = v0;
                    dst[r0 * WS + col0 + 1] = v1;
                }
                const int r1 = mt * 16 + gid + 8;
                if (r1 < TL) {
                    float v2 = c[m][mt][2] + bx, v3 = c[m][mt][3] + by;
                    if (RELU) { v2 = fmaxf(v2, 0.0f); v3 = fmaxf(v3, 0.0f); }
                    dst[r1 * WS + col0] = v2;
                    dst[r1 * WS + col0 + 1] = v3;
                }
            }
        }
    }
}

// ---------------- main kernel ----------------
__global__ void __launch_bounds__(NTHREADS, 1) encoder_kernel(
    const int* __restrict__ tokens, const float* __restrict__ emb,
    const float* __restrict__ bq, const float* __restrict__ bk,
    const float* __restrict__ bv, const float* __restrict__ b1,
    const float* __restrict__ b2,
    const float* __restrict__ lng, const float* __restrict__ lnb,
    float* __restrict__ out)
{
    extern __shared__ char smem[];
    const uint32_t smem_u32 = (uint32_t)__cvta_generic_to_shared(smem);
    float* sx   = (float*)(smem + SM_SX);
    float* bufA = (float*)(smem + SM_A);
    float* bufB = (float*)(smem + SM_B);
    float* bufV = (float*)(smem + SM_V);
    float* sS   = (float*)(smem + SM_SS);
    float* km   = (float*)(smem + SM_KM);

    const int tid = threadIdx.x;
    const int b = blockIdx.x;
    const int warp = tid >> 5, lane = tid & 31;

    // zero A bf16 buffers (padding rows/cols stay zero forever)
    {
        uint32_t* az = (uint32_t*)(smem + SM_AHI);
        for (int i = tid; i < (2 * 64 * KSPAD) / 2; i += NTHREADS) az[i] = 0u;
    }
    // Embedding gather: sx = emb[tokens[b]]  (stride WS)
    {
        const int* tok = tokens + b * TL;
        for (int idx = tid; idx < TL * (TD / 4); idx += NTHREADS) {
            const int m = idx / (TD / 4);
            const int c = idx - m * (TD / 4);
            const int t = __ldg(tok + m);
            *(float4*)(sx + m * WS + c * 4) =
                __ldg((const float4*)emb + (size_t)t * (TD / 4) + c);
        }
    }
    __syncthreads();

    for (int blk = 0; blk < NBLK; blk++) {
        const int m0 = blk * 5;
        const float* bq_ = bq + blk * TD;
        const float* bk_ = bk + blk * TD;
        const float* bv_ = bv + blk * TD;
        const float* b1_ = b1 + blk * TD;
        const float* b2_ = b2 + blk * TD;
        const float* g_  = lng + blk * TD;
        const float* be_ = lnb + blk * TD;

        // Row masks: km[r] = 1 if sum(x[r,:]) == 0
        for (int r = warp; r < TL; r += NTHREADS / 32) {
            float s = 0.0f;
            for (int c = lane; c < TD; c += 32) s += sx[r * WS + c];
            s = wsum(s);
            if (lane == 0) km[r] = (s == 0.0f) ? 1.0f : 0.0f;
        }
        convert_A(sx, smem, tid);
        __syncthreads();

        // Q|K fused, then V — disjoint outputs, shared read-only A: no sync between
        {
            float* dsts2[2] = {bufA, bufB};
            const float* biases2[2] = {bq_, bk_};
            gemm_mma_f<2, true>(g_wfrag + (size_t)m0 * MATSTRIDE, dsts2, biases2,
                                smem_u32, tid);
            float* dsts1[1] = {bufV};
            const float* biases1[1] = {bv_};
            gemm_mma_f<1, true>(g_wfrag + (size_t)(m0 + 2) * MATSTRIDE, dsts1, biases1,
                                smem_u32, tid);
        }
        __syncthreads();

        // scores = (Q @ K^T)*scale with key mask  (SIMT FFMA2)
        if (tid < 500) {
            const int q = tid / 10;
            const int kk0 = (tid % 10) * 5;
            uint64_t acc[5] = {0ull, 0ull, 0ull, 0ull, 0ull};
#pragma unroll 2
            for (int d = 0; d < TD; d += 4) {
                const float4 qa = *(const float4*)(bufA + q * WS + d);
                const uint64_t q01 = pack2(qa.x, qa.y);
                const uint64_t q23 = pack2(qa.z, qa.w);
#pragma unroll
                for (int j = 0; j < 5; j++) {
                    const float4 kv = *(const float4*)(bufB + (kk0 + j) * WS + d);
                    ffma2(acc[j], q01, pack2(kv.x, kv.y));
                    ffma2(acc[j], q23, pack2(kv.z, kv.w));
                }
            }
            const float scale = 0.07071067811865475f;  // 1/sqrt(200)
#pragma unroll
            for (int j = 0; j < 5; j++) {
                float l, h;
                unpack2(acc[j], l, h);
                sS[q * SSTRIDE + kk0 + j] =
                    (km[kk0 + j] != 0.0f) ? NEGV : (l + h) * scale;
            }
        }
        __syncthreads();

        // Softmax rows + query mask
        for (int q = warp; q < TL; q += NTHREADS / 32) {
            const float a  = sS[q * SSTRIDE + lane];
            const float bb = (lane < TL - 32) ? sS[q * SSTRIDE + 32 + lane] : -3.4e38f;
            const float mx = wmax(fmaxf(a, bb));
            const float ea = expf(a - mx);
            const float eb = (lane < TL - 32) ? expf(bb - mx) : 0.0f;
            const float ssum = wsum(ea + eb);
            const float fac = (1.0f - km[q]) / ssum;
            sS[q * SSTRIDE + lane] = ea * fac;
            if (lane < TL - 32) sS[q * SSTRIDE + 32 + lane] = eb * fac;
        }
        __syncthreads();

        // x += attn @ V  (SIMT FFMA2)
        if (tid < 500) {
            const int cg = tid % 50, rg = tid / 50;
            const int n0 = cg * 4, mr = rg * 5;
            uint64_t acc[5][2];
#pragma unroll
            for (int i = 0; i < 5; i++) { acc[i][0] = 0ull; acc[i][1] = 0ull; }
#pragma unroll 2
            for (int kk = 0; kk < TL; kk++) {
                const float4 v = *(const float4*)(bufV + kk * WS + n0);
                const uint64_t v01 = pack2(v.x, v.y);
                const uint64_t v23 = pack2(v.z, v.w);
#pragma unroll
                for (int i = 0; i < 5; i++) {
                    const uint64_t a = rep2(sS[(mr + i) * SSTRIDE + kk]);
                    ffma2(acc[i][0], a, v01);
                    ffma2(acc[i][1], a, v23);
                }
            }
#pragma unroll
            for (int i = 0; i < 5; i++) {
                float a0, a1, a2, a3;
                unpack2(acc[i][0], a0, a1);
                unpack2(acc[i][1], a2, a3);
                float* o = sx + (mr + i) * WS + n0;
                o[0] += a0; o[1] += a1; o[2] += a2; o[3] += a3;
            }
        }
        __syncthreads();

        // FFN1: h1 = relu(x @ W1 + b1) -> bufA
        convert_A(sx, smem, tid);
        __syncthreads();
        {
            float* dsts[1] = {bufA};
            const float* biases[1] = {b1_};
            gemm_mma_f<1, true>(g_wfrag + (size_t)(m0 + 3) * MATSTRIDE, dsts, biases,
                                smem_u32, tid);
        }
        __syncthreads();

        // FFN2: h2 = h1 @ W2 + b2 -> bufB
        convert_A(bufA, smem, tid);
        __syncthreads();
        {
            float* dsts[1] = {bufB};
            const float* biases[1] = {b2_};
            gemm_mma_f<1, false>(g_wfrag + (size_t)(m0 + 4) * MATSTRIDE, dsts, biases,
                                 smem_u32, tid);
        }
        __syncthreads();

        // LayerNorm(h2)*g + be, residual into sx
        for (int r = warp; r < TL; r += NTHREADS / 32) {
            float hbuf[7];
            int nc = 0;
            float s = 0.0f;
            for (int c = lane; c < TD; c += 32) {
                const float h = bufB[r * WS + c];
                hbuf[nc++] = h;
                s += h;
            }
            s = wsum(s);
            const float mu = s * (1.0f / TD);
            float v = 0.0f;
            for (int i = 0; i < nc; i++) {
                const float dd = hbuf[i] - mu;
                v = fmaf(dd, dd, v);
            }
            v = wsum(v);
            const float inv = rsqrtf(v * (1.0f / TD) + LNEPS);
            nc = 0;
            for (int c = lane; c < TD; c += 32) {
                const float y = (hbuf[nc++] - mu) * inv * __ldg(g_ + c) + __ldg(be_ + c);
                sx[r * WS + c] += y;
            }
        }
        __syncthreads();
    }

    // Write out (dense 200 stride)
    {
        float4* o = (float4*)(out + (size_t)b * TL * TD);
        for (int idx = tid; idx < TL * (TD / 4); idx += NTHREADS) {
            const int m = idx / (TD / 4);
            const int c = idx - m * (TD / 4);
            o[idx] = *(const float4*)(sx + m * WS + c * 4);
        }
    }
}

extern "C" void kernel_launch(void* const* d_in, const int* in_sizes, int n_in,
                              void* d_out, int out_size) {
    const int*   tokens = (const int*)d_in[0];
    const float* emb = (const float*)d_in[1];
    const float* Wq  = (const float*)d_in[2];
    const float* bq  = (const float*)d_in[3];
    const float* Wk  = (const float*)d_in[4];
    const float* bk  = (const float*)d_in[5];
    const float* Wv  = (const float*)d_in[6];
    const float* bv  = (const float*)d_in[7];
    const float* W1  = (const float*)d_in[8];
    const float* b1  = (const float*)d_in[9];
    const float* W2  = (const float*)d_in[10];
    const float* b2  = (const float*)d_in[11];
    const float* lng = (const float*)d_in[12];
    const float* lnb = (const float*)d_in[13];
    float* out = (float*)d_out;

    const int B = in_sizes[0] / TL;

    dim3 pgrid(15, NTILES, 1);
    prep_kernel<<<pgrid, 13 * 32>>>(Wq, Wk, Wv, W1, W2);

    cudaFuncSetAttribute(encoder_kernel,
                         cudaFuncAttributeMaxDynamicSharedMemorySize, SM_TOTAL);
    encoder_kernel<<<B, NTHREADS, SM_TOTAL>>>(tokens, emb, bq, bk, bv, b1, b2,
                                              lng, lnb, out);
}